// round 7
// baseline (speedup 1.0000x reference)
#include <cuda_runtime.h>
#include <math.h>

#define B_   64
#define N_   4096
#define D_   128
#define E_   512
#define S_   8                  // N-splits per batch -> grid 512 = 1 wave
#define GPB  16                 // 16-lane groups per block (256 thr)
#define TS_  (S_*GPB)           // 128 interleaved slot streams per batch

// ---- device scratch (no allocations; 16B-aligned for float4 access) ----
// Replay-safe: g_qdone sticky w/ identical data each launch; g_cdone counts
// cumulatively (mod-8 test).
__device__ __align__(16) float g_q  [B_*D_];
__device__ __align__(16) float g_qa [B_*D_];
__device__ __align__(16) float g_pacc[B_*S_*D_];
__device__ float g_ps [B_*S_];
__device__ int   g_qdone[B_];
__device__ int   g_cdone[B_];

__global__ void __launch_bounds__(256, 4)
fused_kernel(const float* __restrict__ kb,
             const float* __restrict__ vq,
             const int*   __restrict__ ion,
             const float* __restrict__ Wq,
             const float* __restrict__ bq,
             const float* __restrict__ Wa,
             const float* __restrict__ ba_p,
             float*       __restrict__ out)
{
    const int tid   = threadIdx.x;
    const int warp  = tid >> 5, lane = tid & 31;
    const int bs    = blockIdx.x;
    const int b     = bs >> 3;              // / S_
    const int split = bs & (S_ - 1);
    const int grp   = lane >> 4, sub = lane & 15;
    const int gid   = warp * 2 + grp;       // 0..15

    __shared__ int   scnt;
    __shared__ float sM, sba;
    __shared__ __align__(16) float sacc[GPB][132];
    __shared__ float ssum[GPB];
    __shared__ int   slast;

    // ---- per-block meta (independent of producers) ----
    if (warp == 0) {
        // int64 vs int32 decode: values in [0,4096); if int64 (LE) every odd
        // 32-bit word of the first 64 is 0. Detection reads stay in first
        // 256B; word 2*b (<=508B) read only when layout is int64 (512B alloc).
        bool oz   = (ion[2*lane + 1] == 0);
        bool is64 = __all_sync(0xffffffffu, oz);
        if (lane == 0) scnt = is64 ? ion[2*b] : ion[b];
    } else if (warp == 1) {
        // M = max(ba + ||Wa||, 0) >= every logit (Cauchy-Schwarz)
        float t = 0.f;
        #pragma unroll
        for (int i = 0; i < 4; i++) { float wv = Wa[i*32 + lane]; t += wv*wv; }
        #pragma unroll
        for (int off = 16; off > 0; off >>= 1)
            t += __shfl_xor_sync(0xffffffffu, t, off);
        if (lane == 0) { float ba = *ba_p; sba = ba; sM = fmaxf(ba + sqrtf(t), 0.f); }
    }

    // ---- producers (blocks 0..63): q/qa for batch `bs`, then release flag.
    //      Grid is a single wave, so producers are always resident.
    if (bs < B_) {
        const float4* v4 = (const float4*)(vq + (size_t)bs * E_);
        float4 v[4];
        #pragma unroll
        for (int j = 0; j < 4; j++) v[j] = v4[j*32 + lane];
        #pragma unroll 2
        for (int t = 0; t < 16; t++) {
            const int d = warp * 16 + t;
            const float4* w4 = (const float4*)(Wq + (size_t)d * E_);
            float a = 0.f;
            #pragma unroll
            for (int j = 0; j < 4; j++) {
                float4 y = w4[j*32 + lane];
                a += v[j].x*y.x + v[j].y*y.y + v[j].z*y.z + v[j].w*y.w;
            }
            #pragma unroll
            for (int off = 16; off > 0; off >>= 1)
                a += __shfl_xor_sync(0xffffffffu, a, off);
            if (lane == 0) {
                float qv = a + bq[d];
                g_q [bs*D_ + d] = qv;
                g_qa[bs*D_ + d] = qv * Wa[d];
            }
        }
        __syncthreads();
        __threadfence();
        if (tid == 0) *((volatile int*)&g_qdone[bs]) = 1;
    }

    // ---- prefetch first two slots (n<128, n+128<256: always in-bounds),
    //      independent of q -> overlaps the flag spin with DRAM latency.
    const float4* kb4 = (const float4*)(kb + (size_t)b * N_ * D_);
    int n = split * GPB + gid;
    float4 c0[2], c1[2];
    #pragma unroll
    for (int i = 0; i < 2; i++)
        c0[i] = __ldcs(&kb4[(size_t)n*32 + i*16 + sub]);
    #pragma unroll
    for (int i = 0; i < 2; i++)
        c1[i] = __ldcs(&kb4[(size_t)(n + TS_)*32 + i*16 + sub]);

    // ---- acquire q for our batch ----
    while (*((volatile int*)&g_qdone[b]) == 0) __nanosleep(64);
    __threadfence();
    __syncthreads();          // also publishes scnt/sM/sba

    const int   limit   = (scnt == 0) ? N_ : scnt;
    const bool  uniform = (scnt == 0);
    const float M  = sM;
    const float ba = sba;

    float4 q[2], qa[2];
    #pragma unroll
    for (int i = 0; i < 2; i++) {
        q[i]  = ((const float4*)(g_q  + b*D_))[i*16 + sub];
        qa[i] = ((const float4*)(g_qa + b*D_))[i*16 + sub];
    }

    float  s = 0.f;
    float4 acc[2] = {make_float4(0,0,0,0), make_float4(0,0,0,0)};

    // ---- main pass: 2 slots per group per iter, clamped streaming loads.
    //      w = exp(L - M): no online max, pure FMA accumulation; invalid
    //      slots get w = 0 exactly (clamped k stays finite -> 0*k = 0).
    while (true) {
        const bool v0 = n       < limit;
        const bool v1 = n + TS_ < limit;

        #pragma unroll
        for (int t = 0; t < 2; t++) {
            float4* k = t ? c1 : c0;
            const bool v = t ? v1 : v0;
            float dot = 0.f, nrm = 0.f;
            #pragma unroll
            for (int i = 0; i < 2; i++) {
                float px = k[i].x*q[i].x, py = k[i].y*q[i].y;
                float pz = k[i].z*q[i].z, pw = k[i].w*q[i].w;
                nrm += px*px + py*py + pz*pz + pw*pw;
                dot += k[i].x*qa[i].x + k[i].y*qa[i].y
                     + k[i].z*qa[i].z + k[i].w*qa[i].w;
            }
            #pragma unroll
            for (int off = 8; off > 0; off >>= 1) {   // 16-lane reduce
                dot += __shfl_xor_sync(0xffffffffu, dot, off);
                nrm += __shfl_xor_sync(0xffffffffu, nrm, off);
            }
            float L = uniform ? 0.f : (dot * rsqrtf(fmaxf(nrm, 1e-24f)) + ba);
            float w = v ? __expf(L - M) : 0.f;        // L <= M: no overflow
            s += w;
            #pragma unroll
            for (int i = 0; i < 2; i++) {
                acc[i].x += w * k[i].x;  acc[i].y += w * k[i].y;
                acc[i].z += w * k[i].z;  acc[i].w += w * k[i].w;
            }
        }

        n += 2 * TS_;
        if (!__any_sync(0xffffffffu, n < limit)) break;

        const int m0 = min(n,       N_ - 1);
        const int m1 = min(n + TS_, N_ - 1);
        #pragma unroll
        for (int i = 0; i < 2; i++)
            c0[i] = __ldcs(&kb4[(size_t)m0*32 + i*16 + sub]);
        #pragma unroll
        for (int i = 0; i < 2; i++)
            c1[i] = __ldcs(&kb4[(size_t)m1*32 + i*16 + sub]);
    }

    // ---- merge 16 groups of this CTA (132-stride: aligned, conflict-free) ----
    #pragma unroll
    for (int i = 0; i < 2; i++)
        *(float4*)&sacc[gid][(i*16 + sub)*4] = acc[i];
    if (sub == 0) ssum[gid] = s;
    __syncthreads();

    if (tid < D_) {
        float a = 0.f;
        #pragma unroll
        for (int j = 0; j < GPB; j++) a += sacc[j][tid];
        g_pacc[bs*D_ + tid] = a;
    } else if (tid == D_) {
        float t = 0.f;
        #pragma unroll
        for (int j = 0; j < GPB; j++) t += ssum[j];
        g_ps[bs] = t;
    }

    // ---- last block per batch combines the 8 split partials ----
    __threadfence();
    __syncthreads();
    if (tid == 0) {
        int old = atomicAdd(&g_cdone[b], 1);     // cumulative across replays
        slast = ((old & (S_ - 1)) == (S_ - 1));
    }
    __syncthreads();
    if (slast) {
        __threadfence();
        if (tid < D_) {
            float ss = 0.f, av = 0.f;
            #pragma unroll
            for (int i = 0; i < S_; i++) {
                ss += __ldcg(&g_ps[b*S_ + i]);
                av += __ldcg(&g_pacc[(b*S_ + i)*D_ + tid]);
            }
            out[b*D_ + tid] = av / ss;           // ss > 0 always (limit >= 1)
        }
    }
}

extern "C" void kernel_launch(void* const* d_in, const int* in_sizes, int n_in,
                              void* d_out, int out_size)
{
    const float* kb  = (const float*)d_in[0];
    const float* vq  = (const float*)d_in[1];
    const int*   ion = (const int*)  d_in[2];   // int32 or int64, auto-detected
    const float* Wq  = (const float*)d_in[3];
    const float* bq  = (const float*)d_in[4];
    const float* Wa  = (const float*)d_in[5];
    const float* ba  = (const float*)d_in[6];
    float* out = (float*)d_out;

    fused_kernel<<<B_ * S_, 256>>>(kb, vq, ion, Wq, bq, Wa, ba, out);
}

// round 8
// speedup vs baseline: 1.1211x; 1.1211x over previous
#include <cuda_runtime.h>
#include <math.h>

#define B_   64
#define N_   4096
#define D_   128
#define E_   512
#define G_   592               // 148 SMs x 4 CTAs = exactly one wave
#define GPB  16                // 16-lane groups per block
#define PRODB 4                // producer blocks per batch

// ---- device scratch (no allocations; 16B-aligned where float4-accessed) ----
// Replay-safe: g_qcnt / g_fin are cumulative monotonic counters; data arrays
// are rewritten with identical values each replay before being read (reads
// gated by the same-replay ticket barrier).
__device__ __align__(16) float g_q  [B_*D_];
__device__ __align__(16) float g_qa [B_*D_];
__device__ float g_part_acc[(size_t)G_ * B_ * D_];   // ~19.4 MB
__device__ float g_part_s  [G_ * B_];
__device__ int   g_qcnt[B_];
__device__ int   g_fin;

__global__ void __launch_bounds__(256, 4)
fused_kernel(const float* __restrict__ kb,
             const float* __restrict__ vq,
             const int*   __restrict__ ion,
             const float* __restrict__ Wq,
             const float* __restrict__ bq,
             const float* __restrict__ Wa,
             const float* __restrict__ ba_p,
             float*       __restrict__ out)
{
    const int tid  = threadIdx.x;
    const int warp = tid >> 5, lane = tid & 31;
    const int bid  = blockIdx.x;
    const int grp  = lane >> 4, sub = lane & 15;
    const int gid  = warp * 2 + grp;        // 0..15

    __shared__ int      sP[B_ + 1];         // exclusive prefix of limits
    __shared__ unsigned suE, suO;           // uniform-batch bitmasks
    __shared__ float    sM, sba;
    __shared__ __align__(16) float sacc[GPB][132];
    __shared__ float    ssum[GPB];
    __shared__ int      sticket;

    // ---- meta: limits, prefix sum, uniform mask (warp 0); M bound (warp 1) ----
    if (warp == 0) {
        // int64 vs int32 decode: values in [0,4096); if int64 (LE) every odd
        // 32-bit word of the first 64 is 0. Detection reads stay in first
        // 256B; int64-mode reads go up to word 126 (<512B alloc).
        bool oz   = (ion[2*lane + 1] == 0);
        bool is64 = __all_sync(0xffffffffu, oz);
        int c0 = is64 ? ion[4*lane]     : ion[2*lane];
        int c1 = is64 ? ion[4*lane + 2] : ion[2*lane + 1];
        unsigned be = __ballot_sync(0xffffffffu, c0 == 0);
        unsigned bo = __ballot_sync(0xffffffffu, c1 == 0);
        int e0 = (c0 == 0) ? N_ : c0;       // cnt==0 -> uniform over all N
        int e1 = (c1 == 0) ? N_ : c1;
        int pair = e0 + e1, scan = pair;
        #pragma unroll
        for (int off = 1; off < 32; off <<= 1) {
            int t = __shfl_up_sync(0xffffffffu, scan, off);
            if (lane >= off) scan += t;
        }
        sP[2*lane]     = scan - pair;
        sP[2*lane + 1] = scan - e1;
        if (lane == 31) sP[B_] = scan;
        if (lane == 0) { suE = be; suO = bo; }
    } else if (warp == 1) {
        // M = max(ba + ||Wa||, 0) >= every logit (Cauchy-Schwarz)
        float t = 0.f;
        #pragma unroll
        for (int i = 0; i < 4; i++) { float wv = Wa[i*32 + lane]; t += wv*wv; }
        #pragma unroll
        for (int off = 16; off > 0; off >>= 1)
            t += __shfl_xor_sync(0xffffffffu, t, off);
        if (lane == 0) { float ba = *ba_p; sba = ba; sM = fmaxf(ba + sqrtf(t), 0.f); }
    }

    // ---- producers: blocks 0..255, 4 per batch, 32 outputs each ----
    if (bid < B_ * PRODB) {
        const int pb  = bid >> 2;
        const int qtr = bid & 3;
        const float4* v4 = (const float4*)(vq + (size_t)pb * E_);
        float4 v[4];
        #pragma unroll
        for (int j = 0; j < 4; j++) v[j] = v4[j*32 + lane];
        #pragma unroll
        for (int t = 0; t < 4; t++) {
            const int d = qtr * 32 + warp * 4 + t;
            const float4* w4 = (const float4*)(Wq + (size_t)d * E_);
            float a = 0.f;
            #pragma unroll
            for (int j = 0; j < 4; j++) {
                float4 y = w4[j*32 + lane];
                a += v[j].x*y.x + v[j].y*y.y + v[j].z*y.z + v[j].w*y.w;
            }
            #pragma unroll
            for (int off = 16; off > 0; off >>= 1)
                a += __shfl_xor_sync(0xffffffffu, a, off);
            if (lane == 0) {
                float qv = a + bq[d];
                g_q [pb*D_ + d] = qv;
                g_qa[pb*D_ + d] = qv * Wa[d];
            }
        }
        __syncthreads();
        __threadfence();
        if (tid == 0) atomicAdd(&g_qcnt[pb], 1);
    }
    __syncthreads();            // publish sP / sM / sba / masks

    const int W = sP[B_];
    const float M  = sM;
    const float ba = sba;

    // ---- balanced contiguous global-slot range for this block ----
    int g  = (int)((long long)bid       * W / G_);
    const int hi = (int)((long long)(bid + 1) * W / G_);
    int b = 0;

    while (g < hi) {
        while (g >= sP[b + 1]) b++;                 // locate batch (ascending)
        const int segEnd = min(hi, sP[b + 1]);
        const int n0 = g - sP[b];
        const int n1 = segEnd - sP[b];
        const bool uniform = (((b & 1) ? suO : suE) >> (b >> 1)) & 1u;

        // wait for q of this batch (counter >= PRODB; cumulative across
        // replays -> instant pass later, benign: identical data rewritten)
        while (*((volatile int*)&g_qcnt[b]) < PRODB) __nanosleep(64);
        __threadfence();

        float4 q[2], qa[2];
        #pragma unroll
        for (int i = 0; i < 2; i++) {
            q[i]  = ((const float4*)(g_q  + b*D_))[i*16 + sub];
            qa[i] = ((const float4*)(g_qa + b*D_))[i*16 + sub];
        }

        const float4* kb4 = (const float4*)(kb + (size_t)b * N_ * D_);
        float  s = 0.f;
        float4 acc[2] = {make_float4(0,0,0,0), make_float4(0,0,0,0)};

        // 2 slots per group per round; clamped loads, w=0 kills invalid slots
        for (int base = n0; base < n1; base += 2*GPB) {
            const int sA = base + gid, sB = sA + GPB;
            const bool vA = sA < n1, vB = sB < n1;
            const int mA = min(sA, n1 - 1), mB = min(sB, n1 - 1);
            float4 kA[2], kB[2];
            #pragma unroll
            for (int i = 0; i < 2; i++)
                kA[i] = __ldcs(&kb4[(size_t)mA*32 + i*16 + sub]);
            #pragma unroll
            for (int i = 0; i < 2; i++)
                kB[i] = __ldcs(&kb4[(size_t)mB*32 + i*16 + sub]);

            #pragma unroll
            for (int t = 0; t < 2; t++) {
                float4* k = t ? kB : kA;
                const bool v = t ? vB : vA;
                float dot = 0.f, nrm = 0.f;
                #pragma unroll
                for (int i = 0; i < 2; i++) {
                    float px = k[i].x*q[i].x, py = k[i].y*q[i].y;
                    float pz = k[i].z*q[i].z, pw = k[i].w*q[i].w;
                    nrm += px*px + py*py + pz*pz + pw*pw;
                    dot += k[i].x*qa[i].x + k[i].y*qa[i].y
                         + k[i].z*qa[i].z + k[i].w*qa[i].w;
                }
                #pragma unroll
                for (int off = 8; off > 0; off >>= 1) {   // 16-lane reduce
                    dot += __shfl_xor_sync(0xffffffffu, dot, off);
                    nrm += __shfl_xor_sync(0xffffffffu, nrm, off);
                }
                float L = uniform ? 0.f : (dot * rsqrtf(fmaxf(nrm, 1e-24f)) + ba);
                float w = v ? __expf(L - M) : 0.f;        // L <= M: no overflow
                s += w;
                #pragma unroll
                for (int i = 0; i < 2; i++) {
                    acc[i].x += w * k[i].x;  acc[i].y += w * k[i].y;
                    acc[i].z += w * k[i].z;  acc[i].w += w * k[i].w;
                }
            }
        }

        // flush this segment's partial to (bid, b)
        __syncthreads();        // protect sacc reuse across segments
        #pragma unroll
        for (int i = 0; i < 2; i++)
            *(float4*)&sacc[gid][(i*16 + sub)*4] = acc[i];
        if (sub == 0) ssum[gid] = s;
        __syncthreads();
        if (tid < D_) {
            float a = 0.f;
            #pragma unroll
            for (int j = 0; j < GPB; j++) a += sacc[j][tid];
            g_part_acc[((size_t)bid*B_ + b)*D_ + tid] = a;
        } else if (tid == D_) {
            float t = 0.f;
            #pragma unroll
            for (int j = 0; j < GPB; j++) t += ssum[j];
            g_part_s[bid*B_ + b] = t;
        }
        g = segEnd;
    }

    // ---- ticket; last 64 ticket-takers combine one batch each ----
    __threadfence();
    __syncthreads();
    if (tid == 0) sticket = atomicAdd(&g_fin, 1);     // cumulative
    __syncthreads();
    const int pos  = sticket % G_;
    const int base = sticket - pos;
    if (pos >= G_ - B_) {
        const int cb = pos - (G_ - B_);               // batch to combine
        if (tid == 0) {                               // wait: all G_ of this
            while (*((volatile int*)&g_fin) < base + G_) __nanosleep(64);
        }
        __syncthreads();
        __threadfence();
        const int Pb  = sP[cb], Pb1 = sP[cb + 1];
        // contributing blocks: ranges intersecting [Pb, Pb1)
        int j0 = (int)(((long long)(Pb + 1) * G_ + W - 1) / W) - 1;
        int j1 = (int)(((long long)Pb1 * G_ - 1) / W);
        if (j0 < 0) j0 = 0;
        if (j1 > G_ - 1) j1 = G_ - 1;
        if (tid < D_) {
            float av = 0.f, ss = 0.f;
            for (int j = j0; j <= j1; j++) {
                const int sj = (int)((long long)j       * W / G_);
                const int ej = (int)((long long)(j + 1) * W / G_);
                if (sj == ej) continue;               // empty block wrote nothing
                av += __ldcg(&g_part_acc[((size_t)j*B_ + cb)*D_ + tid]);
                ss += __ldcg(&g_part_s[j*B_ + cb]);
            }
            out[cb*D_ + tid] = av / ss;               // ss > 0 (>=1 slot, w>0)
        }
    }
}

extern "C" void kernel_launch(void* const* d_in, const int* in_sizes, int n_in,
                              void* d_out, int out_size)
{
    const float* kb  = (const float*)d_in[0];
    const float* vq  = (const float*)d_in[1];
    const int*   ion = (const int*)  d_in[2];   // int32 or int64, auto-detected
    const float* Wq  = (const float*)d_in[3];
    const float* bq  = (const float*)d_in[4];
    const float* Wa  = (const float*)d_in[5];
    const float* ba  = (const float*)d_in[6];
    float* out = (float*)d_out;

    fused_kernel<<<G_, 256>>>(kb, vq, ion, Wq, bq, Wa, ba, out);
}